// round 2
// baseline (speedup 1.0000x reference)
#include <cuda_runtime.h>

// ---------------------------------------------------------------------------
// PoetryGPT forward pass, fp32 baseline.
// B=2, T=1024, D=1024, H=16, HD=64, L=8, V=32000, DF=4096
// ---------------------------------------------------------------------------

namespace {
constexpr int BATCH = 2;
constexpr int T     = 1024;
constexpr int D     = 1024;
constexpr int H     = 16;
constexpr int HD    = 64;
constexpr int NL    = 8;
constexpr int VOCAB = 32000;
constexpr int DF    = 4096;
constexpr int MROWS = BATCH * T;      // 2048
}

// Scratch (static device globals; no allocation anywhere)
__device__ float g_h [MROWS * D];
__device__ float g_ln[MROWS * D];
__device__ float g_q [MROWS * D];
__device__ float g_k [MROWS * D];
__device__ float g_v [MROWS * D];
__device__ float g_o [MROWS * D];
__device__ float g_f [MROWS * DF];
__device__ float g_sc[(size_t)BATCH * H * T * T];   // 128 MB
__device__ float g_wt[D * D];

// ---------------------------------------------------------------------------
// Block reductions (blockDim.x == 256 assumed)
// ---------------------------------------------------------------------------
__device__ __forceinline__ float blk_sum(float v) {
    __shared__ float sm[8];
    int lane = threadIdx.x & 31, w = threadIdx.x >> 5;
    #pragma unroll
    for (int o = 16; o; o >>= 1) v += __shfl_xor_sync(0xffffffffu, v, o);
    if (lane == 0) sm[w] = v;
    __syncthreads();
    if (w == 0) {
        float x = (lane < 8) ? sm[lane] : 0.f;
        #pragma unroll
        for (int o = 4; o; o >>= 1) x += __shfl_xor_sync(0xffffffffu, x, o);
        if (lane == 0) sm[0] = x;
    }
    __syncthreads();
    float r = sm[0];
    __syncthreads();
    return r;
}

__device__ __forceinline__ float blk_max(float v) {
    __shared__ float sm[8];
    int lane = threadIdx.x & 31, w = threadIdx.x >> 5;
    #pragma unroll
    for (int o = 16; o; o >>= 1) v = fmaxf(v, __shfl_xor_sync(0xffffffffu, v, o));
    if (lane == 0) sm[w] = v;
    __syncthreads();
    if (w == 0) {
        float x = (lane < 8) ? sm[lane] : -1e30f;
        #pragma unroll
        for (int o = 4; o; o >>= 1) x = fmaxf(x, __shfl_xor_sync(0xffffffffu, x, o));
        if (lane == 0) sm[0] = x;
    }
    __syncthreads();
    float r = sm[0];
    __syncthreads();
    return r;
}

// ---------------------------------------------------------------------------
// Embedding: h[b,t,:] = tok_emb[x[b,t],:] + pos_emb[t,:]
// grid 2048, block 256
// ---------------------------------------------------------------------------
__global__ void embed_kernel(const int* __restrict__ x,
                             const float* __restrict__ tok,
                             const float* __restrict__ pos,
                             float* __restrict__ out) {
    int row = blockIdx.x;
    int t   = row & (T - 1);
    int id  = x[row];
    int c   = threadIdx.x * 4;
    float4 a = *(const float4*)(tok + (size_t)id * D + c);
    float4 p = *(const float4*)(pos + (size_t)t * D + c);
    float4 r; r.x = a.x + p.x; r.y = a.y + p.y; r.z = a.z + p.z; r.w = a.w + p.w;
    *(float4*)(out + (size_t)row * D + c) = r;
}

// ---------------------------------------------------------------------------
// LayerNorm over D=1024; grid 2048, block 256 (4 elems/thread)
// ---------------------------------------------------------------------------
__global__ void layernorm_kernel(const float* __restrict__ x,
                                 const float* __restrict__ g,
                                 const float* __restrict__ b,
                                 float* __restrict__ y) {
    int row = blockIdx.x;
    int c   = threadIdx.x * 4;
    float4 v = *(const float4*)(x + (size_t)row * D + c);
    float mean = blk_sum(v.x + v.y + v.z + v.w) * (1.f / D);
    float dx = v.x - mean, dy = v.y - mean, dz = v.z - mean, dw = v.w - mean;
    float var = blk_sum(dx * dx + dy * dy + dz * dz + dw * dw) * (1.f / D);
    float inv = rsqrtf(var + 1e-5f);
    float4 gv = *(const float4*)(g + c);
    float4 bv = *(const float4*)(b + c);
    float4 o;
    o.x = dx * inv * gv.x + bv.x;
    o.y = dy * inv * gv.y + bv.y;
    o.z = dz * inv * gv.z + bv.z;
    o.w = dw * inv * gv.w + bv.w;
    *(float4*)(y + (size_t)row * D + c) = o;
}

// ---------------------------------------------------------------------------
// Repack Wq/Wk/Wv (H,D,HD) -> row-major (D, H*HD)
// ---------------------------------------------------------------------------
__global__ void repack_kernel(const float* __restrict__ w, float* __restrict__ out) {
    int i = blockIdx.x * 256 + threadIdx.x;       // over 2^20
    int e = i & 63;
    int d = (i >> 6) & 1023;
    int h = i >> 16;
    out[d * D + h * HD + e] = w[i];
}

// ---------------------------------------------------------------------------
// Generic SGEMM: C[M,N] = A[M,K] @ B[K,N] (+bias[n]) (+res[m,n]) (relu)
// M,N multiples of 128, K multiple of 8. block 256, grid (N/128, M/128)
// ---------------------------------------------------------------------------
__global__ void sgemm_kernel(const float* __restrict__ A, const float* __restrict__ B,
                             const float* __restrict__ bias, const float* res,
                             float* C, int N, int K, int relu) {
    __shared__ float As[8][128];
    __shared__ float Bs[8][128];
    int tid = threadIdx.x;
    int tx = tid & 15, ty = tid >> 4;
    const float* Ab = A + (size_t)blockIdx.y * 128 * K;
    const float* Bb = B + blockIdx.x * 128;
    int aRow = tid >> 1, aCol = (tid & 1) * 4;
    int bRow = tid >> 5, bCol = (tid & 31) * 4;
    float acc[8][8] = {};
    for (int k0 = 0; k0 < K; k0 += 8) {
        float4 av = *(const float4*)(Ab + (size_t)aRow * K + k0 + aCol);
        As[aCol + 0][aRow] = av.x;
        As[aCol + 1][aRow] = av.y;
        As[aCol + 2][aRow] = av.z;
        As[aCol + 3][aRow] = av.w;
        *(float4*)&Bs[bRow][bCol] = *(const float4*)(Bb + (size_t)(k0 + bRow) * N + bCol);
        __syncthreads();
        #pragma unroll
        for (int k = 0; k < 8; k++) {
            float4 a0 = *(float4*)&As[k][ty * 4];
            float4 a1 = *(float4*)&As[k][64 + ty * 4];
            float4 b0 = *(float4*)&Bs[k][tx * 4];
            float4 b1 = *(float4*)&Bs[k][64 + tx * 4];
            float ar[8] = {a0.x, a0.y, a0.z, a0.w, a1.x, a1.y, a1.z, a1.w};
            float br[8] = {b0.x, b0.y, b0.z, b0.w, b1.x, b1.y, b1.z, b1.w};
            #pragma unroll
            for (int i = 0; i < 8; i++)
                #pragma unroll
                for (int j = 0; j < 8; j++)
                    acc[i][j] = fmaf(ar[i], br[j], acc[i][j]);
        }
        __syncthreads();
    }
    int rb = blockIdx.y * 128, cb = blockIdx.x * 128;
    #pragma unroll
    for (int i = 0; i < 8; i++) {
        int r = rb + ((i < 4) ? (ty * 4 + i) : (64 + ty * 4 + i - 4));
        #pragma unroll
        for (int half = 0; half < 2; half++) {
            int c = cb + half * 64 + tx * 4;
            float4 v;
            v.x = acc[i][half * 4 + 0];
            v.y = acc[i][half * 4 + 1];
            v.z = acc[i][half * 4 + 2];
            v.w = acc[i][half * 4 + 3];
            if (bias) {
                v.x += bias[c]; v.y += bias[c + 1]; v.z += bias[c + 2]; v.w += bias[c + 3];
            }
            if (res) {
                float4 rv = *(const float4*)(res + (size_t)r * N + c);
                v.x += rv.x; v.y += rv.y; v.z += rv.z; v.w += rv.w;
            }
            if (relu) {
                v.x = fmaxf(v.x, 0.f); v.y = fmaxf(v.y, 0.f);
                v.z = fmaxf(v.z, 0.f); v.w = fmaxf(v.w, 0.f);
            }
            *(float4*)(C + (size_t)r * N + c) = v;
        }
    }
}

// ---------------------------------------------------------------------------
// Attention scores: sc[b,h,t,s] = scale * q.k  (masked -1e30 for s>t)
// q,k layout: [b*T+t][D] with head at column h*64. grid (16,16,32) block 256
// Tiles with s-tile strictly above diagonal are skipped (softmax zero-fills).
// ---------------------------------------------------------------------------
__global__ void attn_scores_kernel(const float* __restrict__ q,
                                   const float* __restrict__ k,
                                   float* __restrict__ sc) {
    int bh = blockIdx.z;
    int b = bh >> 4, h = bh & 15;
    int t0 = blockIdx.y * 64, s0 = blockIdx.x * 64;
    if (s0 > t0) return;
    __shared__ float Qs[64][68];
    __shared__ float Ks[64][68];
    int tid = threadIdx.x;
    const float* qb = q + (size_t)(b * T) * D + h * HD;
    const float* kb = k + (size_t)(b * T) * D + h * HD;
    #pragma unroll
    for (int i = 0; i < 4; i++) {
        int lin = tid + i * 256;
        int row = lin >> 4, c4 = (lin & 15) << 2;
        *(float4*)&Qs[row][c4] = *(const float4*)(qb + (size_t)(t0 + row) * D + c4);
        *(float4*)&Ks[row][c4] = *(const float4*)(kb + (size_t)(s0 + row) * D + c4);
    }
    __syncthreads();
    int tx = tid & 15, ty = tid >> 4;
    float acc[4][4] = {};
    #pragma unroll 8
    for (int e = 0; e < 64; e++) {
        float qr[4], kr[4];
        #pragma unroll
        for (int i = 0; i < 4; i++) qr[i] = Qs[ty * 4 + i][e];
        #pragma unroll
        for (int j = 0; j < 4; j++) kr[j] = Ks[tx * 4 + j][e];
        #pragma unroll
        for (int i = 0; i < 4; i++)
            #pragma unroll
            for (int j = 0; j < 4; j++)
                acc[i][j] = fmaf(qr[i], kr[j], acc[i][j]);
    }
    const float scale = 0.03125f;   // 1/sqrt(D=1024)  (emb-dim scaling, per reference)
    #pragma unroll
    for (int i = 0; i < 4; i++) {
        int t = t0 + ty * 4 + i;
        #pragma unroll
        for (int j = 0; j < 4; j++) {
            int s = s0 + tx * 4 + j;
            float v = acc[i][j] * scale;
            if (s > t) v = -1e30f;
            sc[((size_t)bh * T + t) * T + s] = v;
        }
    }
}

// ---------------------------------------------------------------------------
// Causal softmax over row [0, t]; zero-fills (t, T). grid 32768, block 256
// ---------------------------------------------------------------------------
__global__ void softmax_kernel(float* __restrict__ sc) {
    int row = blockIdx.x;
    int t = row & (T - 1);
    float* p = sc + (size_t)row * T;
    int n = t + 1, tid = threadIdx.x;
    float m = -1e30f;
    for (int i = tid; i < n; i += 256) m = fmaxf(m, p[i]);
    m = blk_max(m);
    float sum = 0.f;
    for (int i = tid; i < n; i += 256) {
        float e = __expf(p[i] - m);
        p[i] = e;
        sum += e;
    }
    sum = blk_sum(sum);
    float inv = 1.f / sum;
    for (int i = tid; i < n; i += 256) p[i] *= inv;
    for (int i = n + tid; i < T; i += 256) p[i] = 0.f;
}

// ---------------------------------------------------------------------------
// o[b,t,h,:] = P[b,h,t,:] @ V[b,h,:,:]   (causal: s-loop stops at t-tile)
// grid (16 t-tiles, 32 bh), block 256
// ---------------------------------------------------------------------------
__global__ void attn_out_kernel(const float* __restrict__ sc,
                                const float* __restrict__ v,
                                float* __restrict__ o) {
    int bh = blockIdx.y;
    int b = bh >> 4, h = bh & 15;
    int t0 = blockIdx.x * 64;
    __shared__ float Ps[64][68];
    __shared__ float Vs[64][68];
    int tid = threadIdx.x;
    int tx = tid & 15, ty = tid >> 4;
    float acc[4][4] = {};
    const float* vb = v + (size_t)(b * T) * D + h * HD;
    for (int s0 = 0; s0 <= t0; s0 += 64) {
        #pragma unroll
        for (int i = 0; i < 4; i++) {
            int lin = tid + i * 256;
            int row = lin >> 4, c4 = (lin & 15) << 2;
            *(float4*)&Ps[row][c4] = *(const float4*)(sc + ((size_t)bh * T + t0 + row) * T + s0 + c4);
            *(float4*)&Vs[row][c4] = *(const float4*)(vb + (size_t)(s0 + row) * D + c4);
        }
        __syncthreads();
        #pragma unroll 8
        for (int kk = 0; kk < 64; kk++) {
            float4 vr = *(float4*)&Vs[kk][tx * 4];
            float pr[4];
            #pragma unroll
            for (int i = 0; i < 4; i++) pr[i] = Ps[ty * 4 + i][kk];
            #pragma unroll
            for (int i = 0; i < 4; i++) {
                acc[i][0] = fmaf(pr[i], vr.x, acc[i][0]);
                acc[i][1] = fmaf(pr[i], vr.y, acc[i][1]);
                acc[i][2] = fmaf(pr[i], vr.z, acc[i][2]);
                acc[i][3] = fmaf(pr[i], vr.w, acc[i][3]);
            }
        }
        __syncthreads();
    }
    #pragma unroll
    for (int i = 0; i < 4; i++) {
        float4 w;
        w.x = acc[i][0]; w.y = acc[i][1]; w.z = acc[i][2]; w.w = acc[i][3];
        *(float4*)(o + (size_t)(b * T + t0 + ty * 4 + i) * D + h * HD + tx * 4) = w;
    }
}

// ---------------------------------------------------------------------------
// Host orchestration
// ---------------------------------------------------------------------------
extern "C" void kernel_launch(void* const* d_in, const int* in_sizes, int n_in,
                              void* d_out, int out_size) {
    (void)in_sizes; (void)n_in; (void)out_size;
    const int*   x      = (const int*)  d_in[0];
    const float* tok    = (const float*)d_in[1];
    const float* pos    = (const float*)d_in[2];
    const float* Wq     = (const float*)d_in[3];
    const float* Wk     = (const float*)d_in[4];
    const float* Wv     = (const float*)d_in[5];
    const float* Wproj  = (const float*)d_in[6];
    const float* bproj  = (const float*)d_in[7];
    const float* ln1_g  = (const float*)d_in[8];
    const float* ln1_b  = (const float*)d_in[9];
    const float* ln2_g  = (const float*)d_in[10];
    const float* ln2_b  = (const float*)d_in[11];
    const float* W1     = (const float*)d_in[12];
    const float* b1     = (const float*)d_in[13];
    const float* W2     = (const float*)d_in[14];
    const float* b2     = (const float*)d_in[15];
    const float* lnf_g  = (const float*)d_in[16];
    const float* lnf_b  = (const float*)d_in[17];
    const float* Wlm    = (const float*)d_in[18];
    const float* blm    = (const float*)d_in[19];
    float* out = (float*)d_out;

    float *h_, *ln_, *q_, *k_, *v_, *o_, *f_, *sc_, *wt_;
    cudaGetSymbolAddress((void**)&h_,  g_h);
    cudaGetSymbolAddress((void**)&ln_, g_ln);
    cudaGetSymbolAddress((void**)&q_,  g_q);
    cudaGetSymbolAddress((void**)&k_,  g_k);
    cudaGetSymbolAddress((void**)&v_,  g_v);
    cudaGetSymbolAddress((void**)&o_,  g_o);
    cudaGetSymbolAddress((void**)&f_,  g_f);
    cudaGetSymbolAddress((void**)&sc_, g_sc);
    cudaGetSymbolAddress((void**)&wt_, g_wt);

    embed_kernel<<<MROWS, 256>>>(x, tok, pos, h_);

    for (int l = 0; l < NL; l++) {
        const float* wq = Wq + (size_t)l * H * D * HD;
        const float* wk = Wk + (size_t)l * H * D * HD;
        const float* wv = Wv + (size_t)l * H * D * HD;

        layernorm_kernel<<<MROWS, 256>>>(h_, ln1_g + l * D, ln1_b + l * D, ln_);

        // QKV projections (repack weight to [D, H*HD] row-major, then GEMM)
        repack_kernel<<<4096, 256>>>(wq, wt_);
        sgemm_kernel<<<dim3(D / 128, MROWS / 128), 256>>>(ln_, wt_, nullptr, nullptr, q_, D, D, 0);
        repack_kernel<<<4096, 256>>>(wk, wt_);
        sgemm_kernel<<<dim3(D / 128, MROWS / 128), 256>>>(ln_, wt_, nullptr, nullptr, k_, D, D, 0);
        repack_kernel<<<4096, 256>>>(wv, wt_);
        sgemm_kernel<<<dim3(D / 128, MROWS / 128), 256>>>(ln_, wt_, nullptr, nullptr, v_, D, D, 0);

        // Attention
        attn_scores_kernel<<<dim3(T / 64, T / 64, BATCH * H), 256>>>(q_, k_, sc_);
        softmax_kernel<<<BATCH * H * T, 256>>>(sc_);
        attn_out_kernel<<<dim3(T / 64, BATCH * H), 256>>>(sc_, v_, o_);

        // Output projection + residual
        sgemm_kernel<<<dim3(D / 128, MROWS / 128), 256>>>(
            o_, Wproj + (size_t)l * D * D, bproj + l * D, h_, h_, D, D, 0);

        // MLP
        layernorm_kernel<<<MROWS, 256>>>(h_, ln2_g + l * D, ln2_b + l * D, ln_);
        sgemm_kernel<<<dim3(DF / 128, MROWS / 128), 256>>>(
            ln_, W1 + (size_t)l * D * DF, b1 + l * DF, nullptr, f_, DF, D, 1);
        sgemm_kernel<<<dim3(D / 128, MROWS / 128), 256>>>(
            f_, W2 + (size_t)l * DF * D, b2 + l * D, h_, h_, D, DF, 0);
    }

    // Final LN + LM head
    layernorm_kernel<<<MROWS, 256>>>(h_, lnf_g, lnf_b, ln_);
    sgemm_kernel<<<dim3(VOCAB / 128, MROWS / 128), 256>>>(
        ln_, Wlm, blm, nullptr, out, VOCAB, D, 0);
}

// round 4
// speedup vs baseline: 3.5246x; 3.5246x over previous
#include <cuda_runtime.h>
#include <cuda_fp16.h>
#include <cstdint>

// ---------------------------------------------------------------------------
// PoetryGPT forward: fp16 HMMA (mma.sync) GEMMs + fp32 attention/LN/softmax
// B=2, T=1024, D=1024, H=16, HD=64, L=8, V=32000, DF=4096
// ---------------------------------------------------------------------------

namespace {
constexpr int BATCH = 2;
constexpr int T     = 1024;
constexpr int D     = 1024;
constexpr int H     = 16;
constexpr int HD    = 64;
constexpr int NL    = 8;
constexpr int VOCAB = 32000;
constexpr int DF    = 4096;
constexpr int MROWS = BATCH * T;      // 2048
}

// Scratch (static device globals; no allocation anywhere)
__device__ float  g_h [MROWS * D];
__device__ float  g_ln[MROWS * D];
__device__ float  g_q [MROWS * D];
__device__ float  g_k [MROWS * D];
__device__ float  g_v [MROWS * D];
__device__ float  g_o [MROWS * D];
__device__ float  g_f [MROWS * DF];
__device__ float  g_sc[(size_t)BATCH * H * T * T];     // 128 MB
__device__ __half g_a16[(size_t)MROWS * DF];           // act, fp16
__device__ __half g_b16[(size_t)VOCAB * D];            // weightT, fp16

// ---------------------------------------------------------------------------
__device__ __forceinline__ uint32_t smem_u32(const void* p) {
    uint32_t a;
    asm("{ .reg .u64 t; cvta.to.shared.u64 t, %1; cvt.u32.u64 %0, t; }"
        : "=r"(a) : "l"(p));
    return a;
}
#define CP_ASYNC16(sa, gp) \
    asm volatile("cp.async.cg.shared.global [%0], [%1], 16;" :: "r"(sa), "l"(gp))
#define CP_COMMIT() asm volatile("cp.async.commit_group;" ::: "memory")

__device__ __forceinline__ void ldmatrix_x4(uint32_t& r0, uint32_t& r1,
                                            uint32_t& r2, uint32_t& r3,
                                            uint32_t addr) {
    asm volatile("ldmatrix.sync.aligned.m8n8.x4.shared.b16 {%0,%1,%2,%3}, [%4];"
                 : "=r"(r0), "=r"(r1), "=r"(r2), "=r"(r3) : "r"(addr));
}
__device__ __forceinline__ void mma16816(float* c, const uint32_t* a,
                                         const uint32_t* b) {
    asm volatile(
        "mma.sync.aligned.m16n8k16.row.col.f32.f16.f16.f32 "
        "{%0,%1,%2,%3}, {%4,%5,%6,%7}, {%8,%9}, {%0,%1,%2,%3};"
        : "+f"(c[0]), "+f"(c[1]), "+f"(c[2]), "+f"(c[3])
        : "r"(a[0]), "r"(a[1]), "r"(a[2]), "r"(a[3]), "r"(b[0]), "r"(b[1]));
}

// ---------------------------------------------------------------------------
// Block reductions (blockDim.x == 256)
// ---------------------------------------------------------------------------
__device__ __forceinline__ float blk_sum(float v) {
    __shared__ float sm[8];
    int lane = threadIdx.x & 31, w = threadIdx.x >> 5;
    #pragma unroll
    for (int o = 16; o; o >>= 1) v += __shfl_xor_sync(0xffffffffu, v, o);
    if (lane == 0) sm[w] = v;
    __syncthreads();
    if (w == 0) {
        float x = (lane < 8) ? sm[lane] : 0.f;
        #pragma unroll
        for (int o = 4; o; o >>= 1) x += __shfl_xor_sync(0xffffffffu, x, o);
        if (lane == 0) sm[0] = x;
    }
    __syncthreads();
    float r = sm[0];
    __syncthreads();
    return r;
}
__device__ __forceinline__ float blk_max(float v) {
    __shared__ float sm[8];
    int lane = threadIdx.x & 31, w = threadIdx.x >> 5;
    #pragma unroll
    for (int o = 16; o; o >>= 1) v = fmaxf(v, __shfl_xor_sync(0xffffffffu, v, o));
    if (lane == 0) sm[w] = v;
    __syncthreads();
    if (w == 0) {
        float x = (lane < 8) ? sm[lane] : -1e30f;
        #pragma unroll
        for (int o = 4; o; o >>= 1) x = fmaxf(x, __shfl_xor_sync(0xffffffffu, x, o));
        if (lane == 0) sm[0] = x;
    }
    __syncthreads();
    float r = sm[0];
    __syncthreads();
    return r;
}

// ---------------------------------------------------------------------------
// Embedding
// ---------------------------------------------------------------------------
__global__ void embed_kernel(const int* __restrict__ x,
                             const float* __restrict__ tok,
                             const float* __restrict__ pos,
                             float* __restrict__ out) {
    int row = blockIdx.x;
    int t   = row & (T - 1);
    int id  = x[row];
    int c   = threadIdx.x * 4;
    float4 a = *(const float4*)(tok + (size_t)id * D + c);
    float4 p = *(const float4*)(pos + (size_t)t * D + c);
    float4 r; r.x = a.x + p.x; r.y = a.y + p.y; r.z = a.z + p.z; r.w = a.w + p.w;
    *(float4*)(out + (size_t)row * D + c) = r;
}

// ---------------------------------------------------------------------------
// LayerNorm over D=1024
// ---------------------------------------------------------------------------
__global__ void layernorm_kernel(const float* __restrict__ x,
                                 const float* __restrict__ g,
                                 const float* __restrict__ b,
                                 float* __restrict__ y) {
    int row = blockIdx.x;
    int c   = threadIdx.x * 4;
    float4 v = *(const float4*)(x + (size_t)row * D + c);
    float mean = blk_sum(v.x + v.y + v.z + v.w) * (1.f / D);
    float dx = v.x - mean, dy = v.y - mean, dz = v.z - mean, dw = v.w - mean;
    float var = blk_sum(dx * dx + dy * dy + dz * dz + dw * dw) * (1.f / D);
    float inv = rsqrtf(var + 1e-5f);
    float4 gv = *(const float4*)(g + c);
    float4 bv = *(const float4*)(b + c);
    float4 o;
    o.x = dx * inv * gv.x + bv.x;
    o.y = dy * inv * gv.y + bv.y;
    o.z = dz * inv * gv.z + bv.z;
    o.w = dw * inv * gv.w + bv.w;
    *(float4*)(y + (size_t)row * D + c) = o;
}

// ---------------------------------------------------------------------------
// fp32 -> fp16 elementwise (count multiple of 1024)
// ---------------------------------------------------------------------------
__global__ void conv_act_kernel(const float* __restrict__ in, __half* __restrict__ out) {
    size_t i = ((size_t)blockIdx.x * 256 + threadIdx.x) * 4;
    float4 v = *(const float4*)(in + i);
    __half2* o = (__half2*)(out + i);
    o[0] = __floats2half2_rn(v.x, v.y);
    o[1] = __floats2half2_rn(v.z, v.w);
}

// ---------------------------------------------------------------------------
// W [K,N] fp32 -> Bt [N,K] fp16 (tiled transpose). grid (N/32, K/32)
// ---------------------------------------------------------------------------
__global__ void convT_kernel(const float* __restrict__ W, __half* __restrict__ Bt,
                             int K, int N) {
    __shared__ float tbuf[32][33];
    int n0 = blockIdx.x * 32, k0 = blockIdx.y * 32;
    int c = threadIdx.x & 31, r8 = threadIdx.x >> 5;
    #pragma unroll
    for (int i = 0; i < 4; i++) {
        int r = r8 + i * 8;
        tbuf[r][c] = W[(size_t)(k0 + r) * N + n0 + c];
    }
    __syncthreads();
    #pragma unroll
    for (int i = 0; i < 4; i++) {
        int r = r8 + i * 8;
        Bt[(size_t)(n0 + r) * K + k0 + c] = __float2half(tbuf[c][r]);
    }
}

// ---------------------------------------------------------------------------
// Wq (H,D,HD) fp32 -> Bt [(h*64+e), d] fp16. grid (HD/32, D/32, H)
// ---------------------------------------------------------------------------
__global__ void convQKV_kernel(const float* __restrict__ W, __half* __restrict__ Bt) {
    __shared__ float tbuf[32][33];
    int e0 = blockIdx.x * 32, d0 = blockIdx.y * 32, h = blockIdx.z;
    int c = threadIdx.x & 31, r8 = threadIdx.x >> 5;
    #pragma unroll
    for (int i = 0; i < 4; i++) {
        int r = r8 + i * 8;
        tbuf[r][c] = W[((size_t)h * D + d0 + r) * HD + e0 + c];
    }
    __syncthreads();
    #pragma unroll
    for (int i = 0; i < 4; i++) {
        int r = r8 + i * 8;
        Bt[(size_t)(h * HD + e0 + r) * D + d0 + c] = __float2half(tbuf[c][r]);
    }
}

// ---------------------------------------------------------------------------
// HMMA GEMM: C[M,N] = A[M,K] @ Bt[N,K]^T (+bias)(+res)(relu)
// A,Bt fp16 K-major; C fp32. BM=BN=128, BK=32. 256 threads (8 warps, 4x2).
// grid (N/128, M/128). Double-buffered cp.async pipeline.
// ---------------------------------------------------------------------------
__global__ void __launch_bounds__(256)
gemm_mma_kernel(const __half* __restrict__ A, const __half* __restrict__ Bt,
                const float* __restrict__ bias, const float* res,
                float* __restrict__ C, int N, int K, int relu) {
    // 40-half rows (80B stride): ldmatrix row addresses conflict-free
    __shared__ __half sA[2][128 * 40];
    __shared__ __half sB[2][128 * 40];

    int tid = threadIdx.x, lane = tid & 31, wid = tid >> 5;
    int wm = wid & 3, wn = wid >> 2;          // warp tile: rows wm*32, cols wn*64
    size_t m0 = (size_t)blockIdx.y * 128, n0 = (size_t)blockIdx.x * 128;

    // global->smem mapping: 2 chunks/thread/tile (rows r and r+64, seg 16B)
    int lr  = tid >> 2;           // 0..63
    int seg = (tid & 3) * 8;      // half offset of 16B segment

    const __half* Ag0 = A  + (m0 + lr) * (size_t)K + seg;
    const __half* Ag1 = A  + (m0 + lr + 64) * (size_t)K + seg;
    const __half* Bg0 = Bt + (n0 + lr) * (size_t)K + seg;
    const __half* Bg1 = Bt + (n0 + lr + 64) * (size_t)K + seg;

    uint32_t sa0 = smem_u32(&sA[0][lr * 40 + seg]);
    uint32_t sa1 = smem_u32(&sA[0][(lr + 64) * 40 + seg]);
    uint32_t sb0 = smem_u32(&sB[0][lr * 40 + seg]);
    uint32_t sb1 = smem_u32(&sB[0][(lr + 64) * 40 + seg]);
    const uint32_t bufstep = 128 * 40 * 2;    // bytes per buffer

    float acc[2][8][4] = {};
    int nk = K >> 5;

    // prefetch chunk 0 -> buf 0
    CP_ASYNC16(sa0, Ag0);
    CP_ASYNC16(sa1, Ag1);
    CP_ASYNC16(sb0, Bg0);
    CP_ASYNC16(sb1, Bg1);
    CP_COMMIT();

    for (int kb = 0; kb < nk; kb++) {
        bool more = (kb + 1) < nk;
        if (more) {
            uint32_t bo = ((kb + 1) & 1) * bufstep;
            size_t go = (size_t)(kb + 1) * 32;
            CP_ASYNC16(sa0 + bo, Ag0 + go);
            CP_ASYNC16(sa1 + bo, Ag1 + go);
            CP_ASYNC16(sb0 + bo, Bg0 + go);
            CP_ASYNC16(sb1 + bo, Bg1 + go);
            CP_COMMIT();
            asm volatile("cp.async.wait_group 1;" ::: "memory");
        } else {
            asm volatile("cp.async.wait_group 0;" ::: "memory");
        }
        __syncthreads();

        int buf = kb & 1;
        #pragma unroll
        for (int ks = 0; ks < 2; ks++) {
            int kcol = ks * 16 + (lane >> 4) * 8;
            uint32_t a[2][4], b[8][2];
            #pragma unroll
            for (int mt = 0; mt < 2; mt++) {
                uint32_t ad = smem_u32(
                    &sA[buf][(wm * 32 + mt * 16 + (lane & 15)) * 40 + kcol]);
                ldmatrix_x4(a[mt][0], a[mt][1], a[mt][2], a[mt][3], ad);
            }
            #pragma unroll
            for (int nt2 = 0; nt2 < 4; nt2++) {
                uint32_t r0, r1, r2, r3;
                uint32_t bd = smem_u32(
                    &sB[buf][(wn * 64 + nt2 * 16 + (lane & 15)) * 40 + kcol]);
                ldmatrix_x4(r0, r1, r2, r3, bd);
                b[nt2 * 2][0] = r0; b[nt2 * 2][1] = r2;
                b[nt2 * 2 + 1][0] = r1; b[nt2 * 2 + 1][1] = r3;
            }
            #pragma unroll
            for (int mt = 0; mt < 2; mt++)
                #pragma unroll
                for (int nt = 0; nt < 8; nt++)
                    mma16816(acc[mt][nt], a[mt], b[nt]);
        }
        __syncthreads();
    }

    // Epilogue
    int rg = lane >> 2, cg = (lane & 3) * 2;
    #pragma unroll
    for (int mt = 0; mt < 2; mt++) {
        #pragma unroll
        for (int half = 0; half < 2; half++) {
            size_t r = m0 + wm * 32 + mt * 16 + rg + half * 8;
            #pragma unroll
            for (int nt = 0; nt < 8; nt++) {
                size_t c = n0 + wn * 64 + nt * 8 + cg;
                float2 v;
                v.x = acc[mt][nt][half * 2 + 0];
                v.y = acc[mt][nt][half * 2 + 1];
                if (bias) { v.x += bias[c]; v.y += bias[c + 1]; }
                if (res) {
                    float2 rv = *(const float2*)(res + r * N + c);
                    v.x += rv.x; v.y += rv.y;
                }
                if (relu) { v.x = fmaxf(v.x, 0.f); v.y = fmaxf(v.y, 0.f); }
                *(float2*)(C + r * N + c) = v;
            }
        }
    }
}

// ---------------------------------------------------------------------------
// Attention scores (fp32): sc[b,h,t,s] = scale * q.k  (s>t masked)
// ---------------------------------------------------------------------------
__global__ void attn_scores_kernel(const float* __restrict__ q,
                                   const float* __restrict__ k,
                                   float* __restrict__ sc) {
    int bh = blockIdx.z;
    int b = bh >> 4, h = bh & 15;
    int t0 = blockIdx.y * 64, s0 = blockIdx.x * 64;
    if (s0 > t0) return;
    __shared__ float Qs[64][68];
    __shared__ float Ks[64][68];
    int tid = threadIdx.x;
    const float* qb = q + (size_t)(b * T) * D + h * HD;
    const float* kb = k + (size_t)(b * T) * D + h * HD;
    #pragma unroll
    for (int i = 0; i < 4; i++) {
        int lin = tid + i * 256;
        int row = lin >> 4, c4 = (lin & 15) << 2;
        *(float4*)&Qs[row][c4] = *(const float4*)(qb + (size_t)(t0 + row) * D + c4);
        *(float4*)&Ks[row][c4] = *(const float4*)(kb + (size_t)(s0 + row) * D + c4);
    }
    __syncthreads();
    int tx = tid & 15, ty = tid >> 4;
    float acc[4][4] = {};
    #pragma unroll 8
    for (int e = 0; e < 64; e++) {
        float qr[4], kr[4];
        #pragma unroll
        for (int i = 0; i < 4; i++) qr[i] = Qs[ty * 4 + i][e];
        #pragma unroll
        for (int j = 0; j < 4; j++) kr[j] = Ks[tx * 4 + j][e];
        #pragma unroll
        for (int i = 0; i < 4; i++)
            #pragma unroll
            for (int j = 0; j < 4; j++)
                acc[i][j] = fmaf(qr[i], kr[j], acc[i][j]);
    }
    const float scale = 0.03125f;   // 1/sqrt(D=1024) per reference
    #pragma unroll
    for (int i = 0; i < 4; i++) {
        int t = t0 + ty * 4 + i;
        #pragma unroll
        for (int j = 0; j < 4; j++) {
            int s = s0 + tx * 4 + j;
            float v = acc[i][j] * scale;
            if (s > t) v = -1e30f;
            sc[((size_t)bh * T + t) * T + s] = v;
        }
    }
}

// ---------------------------------------------------------------------------
// Causal softmax; zero-fills (t, T)
// ---------------------------------------------------------------------------
__global__ void softmax_kernel(float* __restrict__ sc) {
    int row = blockIdx.x;
    int t = row & (T - 1);
    float* p = sc + (size_t)row * T;
    int n = t + 1, tid = threadIdx.x;
    float m = -1e30f;
    for (int i = tid; i < n; i += 256) m = fmaxf(m, p[i]);
    m = blk_max(m);
    float sum = 0.f;
    for (int i = tid; i < n; i += 256) {
        float e = __expf(p[i] - m);
        p[i] = e;
        sum += e;
    }
    sum = blk_sum(sum);
    float inv = 1.f / sum;
    for (int i = tid; i < n; i += 256) p[i] *= inv;
    for (int i = n + tid; i < T; i += 256) p[i] = 0.f;
}

// ---------------------------------------------------------------------------
// o[b,t,h,:] = P @ V (causal s-loop)
// ---------------------------------------------------------------------------
__global__ void attn_out_kernel(const float* __restrict__ sc,
                                const float* __restrict__ v,
                                float* __restrict__ o) {
    int bh = blockIdx.y;
    int b = bh >> 4, h = bh & 15;
    int t0 = blockIdx.x * 64;
    __shared__ float Ps[64][68];
    __shared__ float Vs[64][68];
    int tid = threadIdx.x;
    int tx = tid & 15, ty = tid >> 4;
    float acc[4][4] = {};
    const float* vb = v + (size_t)(b * T) * D + h * HD;
    for (int s0 = 0; s0 <= t0; s0 += 64) {
        #pragma unroll
        for (int i = 0; i < 4; i++) {
            int lin = tid + i * 256;
            int row = lin >> 4, c4 = (lin & 15) << 2;
            *(float4*)&Ps[row][c4] = *(const float4*)(sc + ((size_t)bh * T + t0 + row) * T + s0 + c4);
            *(float4*)&Vs[row][c4] = *(const float4*)(vb + (size_t)(s0 + row) * D + c4);
        }
        __syncthreads();
        #pragma unroll 8
        for (int kk = 0; kk < 64; kk++) {
            float4 vr = *(float4*)&Vs[kk][tx * 4];
            float pr[4];
            #pragma unroll
            for (int i = 0; i < 4; i++) pr[i] = Ps[ty * 4 + i][kk];
            #pragma unroll
            for (int i = 0; i < 4; i++) {
                acc[i][0] = fmaf(pr[i], vr.x, acc[i][0]);
                acc[i][1] = fmaf(pr[i], vr.y, acc[i][1]);
                acc[i][2] = fmaf(pr[i], vr.z, acc[i][2]);
                acc[i][3] = fmaf(pr[i], vr.w, acc[i][3]);
            }
        }
        __syncthreads();
    }
    #pragma unroll
    for (int i = 0; i < 4; i++) {
        float4 w;
        w.x = acc[i][0]; w.y = acc[i][1]; w.z = acc[i][2]; w.w = acc[i][3];
        *(float4*)(o + (size_t)(b * T + t0 + ty * 4 + i) * D + h * HD + tx * 4) = w;
    }
}

// ---------------------------------------------------------------------------
// Host orchestration
// ---------------------------------------------------------------------------
extern "C" void kernel_launch(void* const* d_in, const int* in_sizes, int n_in,
                              void* d_out, int out_size) {
    (void)in_sizes; (void)n_in; (void)out_size;
    const int*   x      = (const int*)  d_in[0];
    const float* tok    = (const float*)d_in[1];
    const float* pos    = (const float*)d_in[2];
    const float* Wq     = (const float*)d_in[3];
    const float* Wk     = (const float*)d_in[4];
    const float* Wv     = (const float*)d_in[5];
    const float* Wproj  = (const float*)d_in[6];
    const float* bproj  = (const float*)d_in[7];
    const float* ln1_g  = (const float*)d_in[8];
    const float* ln1_b  = (const float*)d_in[9];
    const float* ln2_g  = (const float*)d_in[10];
    const float* ln2_b  = (const float*)d_in[11];
    const float* W1     = (const float*)d_in[12];
    const float* b1     = (const float*)d_in[13];
    const float* W2     = (const float*)d_in[14];
    const float* b2     = (const float*)d_in[15];
    const float* lnf_g  = (const float*)d_in[16];
    const float* lnf_b  = (const float*)d_in[17];
    const float* Wlm    = (const float*)d_in[18];
    const float* blm    = (const float*)d_in[19];
    float* out = (float*)d_out;

    float *h_, *ln_, *q_, *k_, *v_, *o_, *f_, *sc_;
    __half *a16, *b16;
    cudaGetSymbolAddress((void**)&h_,  g_h);
    cudaGetSymbolAddress((void**)&ln_, g_ln);
    cudaGetSymbolAddress((void**)&q_,  g_q);
    cudaGetSymbolAddress((void**)&k_,  g_k);
    cudaGetSymbolAddress((void**)&v_,  g_v);
    cudaGetSymbolAddress((void**)&o_,  g_o);
    cudaGetSymbolAddress((void**)&f_,  g_f);
    cudaGetSymbolAddress((void**)&sc_, g_sc);
    cudaGetSymbolAddress((void**)&a16, g_a16);
    cudaGetSymbolAddress((void**)&b16, g_b16);

    embed_kernel<<<MROWS, 256>>>(x, tok, pos, h_);

    for (int l = 0; l < NL; l++) {
        const float* wq = Wq + (size_t)l * H * D * HD;
        const float* wk = Wk + (size_t)l * H * D * HD;
        const float* wv = Wv + (size_t)l * H * D * HD;

        layernorm_kernel<<<MROWS, 256>>>(h_, ln1_g + l * D, ln1_b + l * D, ln_);
        conv_act_kernel<<<MROWS * D / 1024, 256>>>(ln_, a16);

        // QKV projections
        convQKV_kernel<<<dim3(HD / 32, D / 32, H), 256>>>(wq, b16);
        gemm_mma_kernel<<<dim3(D / 128, MROWS / 128), 256>>>(a16, b16, nullptr, nullptr, q_, D, D, 0);
        convQKV_kernel<<<dim3(HD / 32, D / 32, H), 256>>>(wk, b16);
        gemm_mma_kernel<<<dim3(D / 128, MROWS / 128), 256>>>(a16, b16, nullptr, nullptr, k_, D, D, 0);
        convQKV_kernel<<<dim3(HD / 32, D / 32, H), 256>>>(wv, b16);
        gemm_mma_kernel<<<dim3(D / 128, MROWS / 128), 256>>>(a16, b16, nullptr, nullptr, v_, D, D, 0);

        // Attention (fp32)
        attn_scores_kernel<<<dim3(T / 64, T / 64, BATCH * H), 256>>>(q_, k_, sc_);
        softmax_kernel<<<BATCH * H * T, 256>>>(sc_);
        attn_out_kernel<<<dim3(T / 64, BATCH * H), 256>>>(sc_, v_, o_);

        // Output projection + residual
        conv_act_kernel<<<MROWS * D / 1024, 256>>>(o_, a16);
        convT_kernel<<<dim3(D / 32, D / 32), 256>>>(Wproj + (size_t)l * D * D, b16, D, D);
        gemm_mma_kernel<<<dim3(D / 128, MROWS / 128), 256>>>(a16, b16, bproj + l * D, h_, h_, D, D, 0);

        // MLP
        layernorm_kernel<<<MROWS, 256>>>(h_, ln2_g + l * D, ln2_b + l * D, ln_);
        conv_act_kernel<<<MROWS * D / 1024, 256>>>(ln_, a16);
        convT_kernel<<<dim3(DF / 32, D / 32), 256>>>(W1 + (size_t)l * D * DF, b16, D, DF);
        gemm_mma_kernel<<<dim3(DF / 128, MROWS / 128), 256>>>(a16, b16, b1 + l * DF, nullptr, f_, DF, D, 1);
        conv_act_kernel<<<MROWS * DF / 1024, 256>>>(f_, a16);
        convT_kernel<<<dim3(D / 32, DF / 32), 256>>>(W2 + (size_t)l * DF * D, b16, DF, D);
        gemm_mma_kernel<<<dim3(D / 128, MROWS / 128), 256>>>(a16, b16, b2 + l * D, h_, h_, D, DF, 0);
    }

    // Final LN + LM head
    layernorm_kernel<<<MROWS, 256>>>(h_, lnf_g, lnf_b, ln_);
    conv_act_kernel<<<MROWS * D / 1024, 256>>>(ln_, a16);
    convT_kernel<<<dim3(VOCAB / 32, D / 32), 256>>>(Wlm, b16, D, VOCAB);
    gemm_mma_kernel<<<dim3(VOCAB / 128, MROWS / 128), 256>>>(a16, b16, blm, nullptr, out, VOCAB, D, 0);
}

// round 5
// speedup vs baseline: 6.0702x; 1.7223x over previous
#include <cuda_runtime.h>
#include <cuda_fp16.h>
#include <cstdint>

// ---------------------------------------------------------------------------
// PoetryGPT forward: fp16 HMMA GEMMs + fused flash attention (HMMA)
// B=2, T=1024, D=1024, H=16, HD=64, L=8, V=32000, DF=4096
// ---------------------------------------------------------------------------

namespace {
constexpr int BATCH = 2;
constexpr int T     = 1024;
constexpr int D     = 1024;
constexpr int H     = 16;
constexpr int HD    = 64;
constexpr int NL    = 8;
constexpr int VOCAB = 32000;
constexpr int DF    = 4096;
constexpr int MROWS = BATCH * T;      // 2048
}

// Scratch (static device globals; no allocation anywhere)
__device__ float  g_h    [MROWS * D];
__device__ __half g_a16  [(size_t)MROWS * D];
__device__ __half g_qkv16[(size_t)MROWS * 3 * D];
__device__ __half g_f16  [(size_t)MROWS * DF];
__device__ __half g_o16  [(size_t)MROWS * D];
__device__ __half g_b16  [(size_t)VOCAB * D];

// ---------------------------------------------------------------------------
__device__ __forceinline__ uint32_t smem_u32(const void* p) {
    uint32_t a;
    asm("{ .reg .u64 t; cvta.to.shared.u64 t, %1; cvt.u32.u64 %0, t; }"
        : "=r"(a) : "l"(p));
    return a;
}
#define CP_ASYNC16(sa, gp) \
    asm volatile("cp.async.cg.shared.global [%0], [%1], 16;" :: "r"(sa), "l"(gp))
#define CP_COMMIT() asm volatile("cp.async.commit_group;" ::: "memory")

__device__ __forceinline__ void ldmatrix_x4(uint32_t& r0, uint32_t& r1,
                                            uint32_t& r2, uint32_t& r3,
                                            uint32_t addr) {
    asm volatile("ldmatrix.sync.aligned.m8n8.x4.shared.b16 {%0,%1,%2,%3}, [%4];"
                 : "=r"(r0), "=r"(r1), "=r"(r2), "=r"(r3) : "r"(addr));
}
__device__ __forceinline__ void ldmatrix_x4_trans(uint32_t& r0, uint32_t& r1,
                                                  uint32_t& r2, uint32_t& r3,
                                                  uint32_t addr) {
    asm volatile("ldmatrix.sync.aligned.m8n8.x4.trans.shared.b16 {%0,%1,%2,%3}, [%4];"
                 : "=r"(r0), "=r"(r1), "=r"(r2), "=r"(r3) : "r"(addr));
}
__device__ __forceinline__ void mma16816(float* c, const uint32_t* a,
                                         const uint32_t* b) {
    asm volatile(
        "mma.sync.aligned.m16n8k16.row.col.f32.f16.f16.f32 "
        "{%0,%1,%2,%3}, {%4,%5,%6,%7}, {%8,%9}, {%0,%1,%2,%3};"
        : "+f"(c[0]), "+f"(c[1]), "+f"(c[2]), "+f"(c[3])
        : "r"(a[0]), "r"(a[1]), "r"(a[2]), "r"(a[3]), "r"(b[0]), "r"(b[1]));
}
__device__ __forceinline__ uint32_t h2pack(float x, float y) {
    __half2 h = __floats2half2_rn(x, y);
    return *(uint32_t*)&h;
}

// ---------------------------------------------------------------------------
// Block reductions (blockDim.x == 256)
// ---------------------------------------------------------------------------
__device__ __forceinline__ float blk_sum(float v) {
    __shared__ float sm[8];
    int lane = threadIdx.x & 31, w = threadIdx.x >> 5;
    #pragma unroll
    for (int o = 16; o; o >>= 1) v += __shfl_xor_sync(0xffffffffu, v, o);
    if (lane == 0) sm[w] = v;
    __syncthreads();
    if (w == 0) {
        float x = (lane < 8) ? sm[lane] : 0.f;
        #pragma unroll
        for (int o = 4; o; o >>= 1) x += __shfl_xor_sync(0xffffffffu, x, o);
        if (lane == 0) sm[0] = x;
    }
    __syncthreads();
    float r = sm[0];
    __syncthreads();
    return r;
}

// ---------------------------------------------------------------------------
// Embedding
// ---------------------------------------------------------------------------
__global__ void embed_kernel(const int* __restrict__ x,
                             const float* __restrict__ tok,
                             const float* __restrict__ pos,
                             float* __restrict__ out) {
    int row = blockIdx.x;
    int t   = row & (T - 1);
    int id  = x[row];
    int c   = threadIdx.x * 4;
    float4 a = *(const float4*)(tok + (size_t)id * D + c);
    float4 p = *(const float4*)(pos + (size_t)t * D + c);
    float4 r; r.x = a.x + p.x; r.y = a.y + p.y; r.z = a.z + p.z; r.w = a.w + p.w;
    *(float4*)(out + (size_t)row * D + c) = r;
}

// ---------------------------------------------------------------------------
// LayerNorm over D=1024, fp32 in -> fp16 out
// ---------------------------------------------------------------------------
__global__ void layernorm_kernel(const float* __restrict__ x,
                                 const float* __restrict__ g,
                                 const float* __restrict__ b,
                                 __half* __restrict__ y) {
    int row = blockIdx.x;
    int c   = threadIdx.x * 4;
    float4 v = *(const float4*)(x + (size_t)row * D + c);
    float mean = blk_sum(v.x + v.y + v.z + v.w) * (1.f / D);
    float dx = v.x - mean, dy = v.y - mean, dz = v.z - mean, dw = v.w - mean;
    float var = blk_sum(dx * dx + dy * dy + dz * dz + dw * dw) * (1.f / D);
    float inv = rsqrtf(var + 1e-5f);
    float4 gv = *(const float4*)(g + c);
    float4 bv = *(const float4*)(b + c);
    __half2* o = (__half2*)(y + (size_t)row * D + c);
    o[0] = __floats2half2_rn(dx * inv * gv.x + bv.x, dy * inv * gv.y + bv.y);
    o[1] = __floats2half2_rn(dz * inv * gv.z + bv.z, dw * inv * gv.w + bv.w);
}

// ---------------------------------------------------------------------------
// W [K,N] fp32 -> Bt [N,K] fp16 (tiled transpose). grid (N/32, K/32)
// ---------------------------------------------------------------------------
__global__ void convT_kernel(const float* __restrict__ W, __half* __restrict__ Bt,
                             int K, int N) {
    __shared__ float tbuf[32][33];
    int n0 = blockIdx.x * 32, k0 = blockIdx.y * 32;
    int c = threadIdx.x & 31, r8 = threadIdx.x >> 5;
    #pragma unroll
    for (int i = 0; i < 4; i++) {
        int r = r8 + i * 8;
        tbuf[r][c] = W[(size_t)(k0 + r) * N + n0 + c];
    }
    __syncthreads();
    #pragma unroll
    for (int i = 0; i < 4; i++) {
        int r = r8 + i * 8;
        Bt[(size_t)(n0 + r) * K + k0 + c] = __float2half(tbuf[c][r]);
    }
}

// ---------------------------------------------------------------------------
// Wq (H,D,HD) fp32 -> Bt [(h*64+e), d] fp16. grid (HD/32, D/32, H)
// ---------------------------------------------------------------------------
__global__ void convQKV_kernel(const float* __restrict__ W, __half* __restrict__ Bt) {
    __shared__ float tbuf[32][33];
    int e0 = blockIdx.x * 32, d0 = blockIdx.y * 32, h = blockIdx.z;
    int c = threadIdx.x & 31, r8 = threadIdx.x >> 5;
    #pragma unroll
    for (int i = 0; i < 4; i++) {
        int r = r8 + i * 8;
        tbuf[r][c] = W[((size_t)h * D + d0 + r) * HD + e0 + c];
    }
    __syncthreads();
    #pragma unroll
    for (int i = 0; i < 4; i++) {
        int r = r8 + i * 8;
        Bt[(size_t)(h * HD + e0 + r) * D + d0 + c] = __float2half(tbuf[c][r]);
    }
}

// ---------------------------------------------------------------------------
// HMMA GEMM: C[M,N] = A[M,K] @ Bt[N,K]^T (+bias)(+res)(relu)
// Output fp32 (Cf) or fp16 (Ch). BM=BN=128, BK=32, 8 warps, double-buffered.
// ---------------------------------------------------------------------------
__global__ void __launch_bounds__(256)
gemm_mma_kernel(const __half* __restrict__ A, const __half* __restrict__ Bt,
                const float* __restrict__ bias, const float* res,
                float* __restrict__ Cf, __half* __restrict__ Ch,
                int N, int K, int relu) {
    __shared__ __half sA[2][128 * 40];
    __shared__ __half sB[2][128 * 40];

    int tid = threadIdx.x, lane = tid & 31, wid = tid >> 5;
    int wm = wid & 3, wn = wid >> 2;
    size_t m0 = (size_t)blockIdx.y * 128, n0 = (size_t)blockIdx.x * 128;

    int lr  = tid >> 2;
    int seg = (tid & 3) * 8;

    const __half* Ag0 = A  + (m0 + lr) * (size_t)K + seg;
    const __half* Ag1 = A  + (m0 + lr + 64) * (size_t)K + seg;
    const __half* Bg0 = Bt + (n0 + lr) * (size_t)K + seg;
    const __half* Bg1 = Bt + (n0 + lr + 64) * (size_t)K + seg;

    uint32_t sa0 = smem_u32(&sA[0][lr * 40 + seg]);
    uint32_t sa1 = smem_u32(&sA[0][(lr + 64) * 40 + seg]);
    uint32_t sb0 = smem_u32(&sB[0][lr * 40 + seg]);
    uint32_t sb1 = smem_u32(&sB[0][(lr + 64) * 40 + seg]);
    const uint32_t bufstep = 128 * 40 * 2;

    float acc[2][8][4] = {};
    int nk = K >> 5;

    CP_ASYNC16(sa0, Ag0);
    CP_ASYNC16(sa1, Ag1);
    CP_ASYNC16(sb0, Bg0);
    CP_ASYNC16(sb1, Bg1);
    CP_COMMIT();

    for (int kb = 0; kb < nk; kb++) {
        bool more = (kb + 1) < nk;
        if (more) {
            uint32_t bo = ((kb + 1) & 1) * bufstep;
            size_t go = (size_t)(kb + 1) * 32;
            CP_ASYNC16(sa0 + bo, Ag0 + go);
            CP_ASYNC16(sa1 + bo, Ag1 + go);
            CP_ASYNC16(sb0 + bo, Bg0 + go);
            CP_ASYNC16(sb1 + bo, Bg1 + go);
            CP_COMMIT();
            asm volatile("cp.async.wait_group 1;" ::: "memory");
        } else {
            asm volatile("cp.async.wait_group 0;" ::: "memory");
        }
        __syncthreads();

        int buf = kb & 1;
        #pragma unroll
        for (int ks = 0; ks < 2; ks++) {
            int kcol = ks * 16 + (lane >> 4) * 8;
            uint32_t a[2][4], b[8][2];
            #pragma unroll
            for (int mt = 0; mt < 2; mt++) {
                uint32_t ad = smem_u32(
                    &sA[buf][(wm * 32 + mt * 16 + (lane & 15)) * 40 + kcol]);
                ldmatrix_x4(a[mt][0], a[mt][1], a[mt][2], a[mt][3], ad);
            }
            #pragma unroll
            for (int nt2 = 0; nt2 < 4; nt2++) {
                uint32_t r0, r1, r2, r3;
                uint32_t bd = smem_u32(
                    &sB[buf][(wn * 64 + nt2 * 16 + (lane & 15)) * 40 + kcol]);
                ldmatrix_x4(r0, r1, r2, r3, bd);
                b[nt2 * 2][0] = r0; b[nt2 * 2][1] = r2;
                b[nt2 * 2 + 1][0] = r1; b[nt2 * 2 + 1][1] = r3;
            }
            #pragma unroll
            for (int mt = 0; mt < 2; mt++)
                #pragma unroll
                for (int nt = 0; nt < 8; nt++)
                    mma16816(acc[mt][nt], a[mt], b[nt]);
        }
        __syncthreads();
    }

    int rg = lane >> 2, cg = (lane & 3) * 2;
    #pragma unroll
    for (int mt = 0; mt < 2; mt++) {
        #pragma unroll
        for (int half = 0; half < 2; half++) {
            size_t r = m0 + wm * 32 + mt * 16 + rg + half * 8;
            #pragma unroll
            for (int nt = 0; nt < 8; nt++) {
                size_t c = n0 + wn * 64 + nt * 8 + cg;
                float vx = acc[mt][nt][half * 2 + 0];
                float vy = acc[mt][nt][half * 2 + 1];
                if (bias) { vx += bias[c]; vy += bias[c + 1]; }
                if (res) {
                    float2 rv = *(const float2*)(res + r * N + c);
                    vx += rv.x; vy += rv.y;
                }
                if (relu) { vx = fmaxf(vx, 0.f); vy = fmaxf(vy, 0.f); }
                if (Ch) {
                    *(__half2*)(Ch + r * N + c) = __floats2half2_rn(vx, vy);
                } else {
                    float2 v; v.x = vx; v.y = vy;
                    *(float2*)(Cf + r * N + c) = v;
                }
            }
        }
    }
}

// ---------------------------------------------------------------------------
// Fused causal flash attention (fp16 HMMA, fp32 online softmax)
// qkv: [row][3*D] fp16 (q at h*64, k at 1024+h*64, v at 2048+h*64)
// o16: [row][D] fp16 (concat heads). grid (T/64, BATCH*H), block 128 (4 warps)
// ---------------------------------------------------------------------------
__global__ void __launch_bounds__(128)
flash_attn_kernel(const __half* __restrict__ qkv, __half* __restrict__ o16) {
    constexpr int RS = 3 * D;    // qkv row stride
    constexpr int ST = 72;       // smem row stride (halfs)
    __shared__ __half sQ[64 * ST];
    __shared__ __half sK[2][64 * ST];
    __shared__ __half sV[2][64 * ST];

    int tid = threadIdx.x, lane = tid & 31, wid = tid >> 5;
    int bh = blockIdx.y;
    int b = bh >> 4, h = bh & 15;
    int tt = blockIdx.x, t0 = tt * 64;

    const __half* qb = qkv + (size_t)(b * T) * RS + h * HD;
    const __half* kb = qb + D;
    const __half* vb = qb + 2 * D;

    // load Q tile (64x64)
    int seg = (tid & 7) * 8, rr = tid >> 3;     // rr 0..15
    #pragma unroll
    for (int i = 0; i < 4; i++) {
        int row = rr + i * 16;
        *(uint4*)&sQ[row * ST + seg] =
            *(const uint4*)(qb + (size_t)(t0 + row) * RS + seg);
    }
    __syncthreads();

    // Q a-frags: warp owns rows wid*16..+15
    uint32_t qa[4][4];
    {
        int qr = wid * 16 + (lane & 15);
        #pragma unroll
        for (int kk = 0; kk < 4; kk++) {
            uint32_t ad = smem_u32(&sQ[qr * ST + kk * 16 + (lane >> 4) * 8]);
            ldmatrix_x4(qa[kk][0], qa[kk][1], qa[kk][2], qa[kk][3], ad);
        }
    }

    float m[2] = {-1e30f, -1e30f}, l[2] = {0.f, 0.f};
    float oacc[8][4] = {};
    int nst = tt + 1;

    // prefetch tile 0
    {
        #pragma unroll
        for (int i = 0; i < 4; i++) {
            int row = rr + i * 16;
            const __half* kg = kb + (size_t)row * RS + seg;
            const __half* vg = vb + (size_t)row * RS + seg;
            CP_ASYNC16(smem_u32(&sK[0][row * ST + seg]), kg);
            CP_ASYNC16(smem_u32(&sV[0][row * ST + seg]), vg);
        }
        CP_COMMIT();
    }

    const float scale = 0.03125f;     // 1/sqrt(D=1024) per reference
    int trow0 = t0 + wid * 16 + (lane >> 2);

    for (int st = 0; st < nst; st++) {
        int buf = st & 1;
        asm volatile("cp.async.wait_group 0;" ::: "memory");
        __syncthreads();
        if (st + 1 < nst) {
            int nb = buf ^ 1;
            #pragma unroll
            for (int i = 0; i < 4; i++) {
                int row = rr + i * 16;
                const __half* kg = kb + (size_t)((st + 1) * 64 + row) * RS + seg;
                const __half* vg = vb + (size_t)((st + 1) * 64 + row) * RS + seg;
                CP_ASYNC16(smem_u32(&sK[nb][row * ST + seg]), kg);
                CP_ASYNC16(smem_u32(&sV[nb][row * ST + seg]), vg);
            }
            CP_COMMIT();
        }

        // S = Q K^T  (16x64 per warp)
        float sacc[8][4] = {};
        #pragma unroll
        for (int kk = 0; kk < 4; kk++) {
            uint32_t bfr[8][2];
            #pragma unroll
            for (int j2 = 0; j2 < 4; j2++) {
                uint32_t r0, r1, r2, r3;
                uint32_t ad = smem_u32(
                    &sK[buf][(j2 * 16 + (lane & 15)) * ST + kk * 16 + (lane >> 4) * 8]);
                ldmatrix_x4(r0, r1, r2, r3, ad);
                bfr[j2 * 2][0] = r0; bfr[j2 * 2][1] = r2;
                bfr[j2 * 2 + 1][0] = r1; bfr[j2 * 2 + 1][1] = r3;
            }
            #pragma unroll
            for (int j = 0; j < 8; j++)
                mma16816(sacc[j], qa[kk], bfr[j]);
        }

        // scale + causal mask (diag tile only)
        bool diag = (st == tt);
        #pragma unroll
        for (int j = 0; j < 8; j++) {
            #pragma unroll
            for (int q = 0; q < 4; q++) {
                float v = sacc[j][q] * scale;
                if (diag) {
                    int s = st * 64 + j * 8 + (lane & 3) * 2 + (q & 1);
                    int t = trow0 + ((q < 2) ? 0 : 8);
                    if (s > t) v = -1e30f;
                }
                sacc[j][q] = v;
            }
        }

        // online softmax
        float mx0 = -1e30f, mx1 = -1e30f;
        #pragma unroll
        for (int j = 0; j < 8; j++) {
            mx0 = fmaxf(mx0, fmaxf(sacc[j][0], sacc[j][1]));
            mx1 = fmaxf(mx1, fmaxf(sacc[j][2], sacc[j][3]));
        }
        #pragma unroll
        for (int o = 1; o <= 2; o <<= 1) {
            mx0 = fmaxf(mx0, __shfl_xor_sync(0xffffffffu, mx0, o));
            mx1 = fmaxf(mx1, __shfl_xor_sync(0xffffffffu, mx1, o));
        }
        float mn0 = fmaxf(m[0], mx0), mn1 = fmaxf(m[1], mx1);
        float a0 = __expf(m[0] - mn0), a1 = __expf(m[1] - mn1);
        m[0] = mn0; m[1] = mn1;

        float s0 = 0.f, s1 = 0.f;
        #pragma unroll
        for (int j = 0; j < 8; j++) {
            sacc[j][0] = __expf(sacc[j][0] - mn0);
            sacc[j][1] = __expf(sacc[j][1] - mn0);
            sacc[j][2] = __expf(sacc[j][2] - mn1);
            sacc[j][3] = __expf(sacc[j][3] - mn1);
            s0 += sacc[j][0] + sacc[j][1];
            s1 += sacc[j][2] + sacc[j][3];
        }
        #pragma unroll
        for (int o = 1; o <= 2; o <<= 1) {
            s0 += __shfl_xor_sync(0xffffffffu, s0, o);
            s1 += __shfl_xor_sync(0xffffffffu, s1, o);
        }
        l[0] = l[0] * a0 + s0;
        l[1] = l[1] * a1 + s1;
        #pragma unroll
        for (int j = 0; j < 8; j++) {
            oacc[j][0] *= a0; oacc[j][1] *= a0;
            oacc[j][2] *= a1; oacc[j][3] *= a1;
        }

        // O += P V   (P a-frags come from S c-frags in-register)
        #pragma unroll
        for (int kk = 0; kk < 4; kk++) {
            uint32_t pa[4];
            pa[0] = h2pack(sacc[2 * kk][0], sacc[2 * kk][1]);
            pa[1] = h2pack(sacc[2 * kk][2], sacc[2 * kk][3]);
            pa[2] = h2pack(sacc[2 * kk + 1][0], sacc[2 * kk + 1][1]);
            pa[3] = h2pack(sacc[2 * kk + 1][2], sacc[2 * kk + 1][3]);
            uint32_t vfr[8][2];
            #pragma unroll
            for (int j2 = 0; j2 < 4; j2++) {
                uint32_t r0, r1, r2, r3;
                uint32_t ad = smem_u32(
                    &sV[buf][(kk * 16 + (lane & 15)) * ST + j2 * 16 + (lane >> 4) * 8]);
                ldmatrix_x4_trans(r0, r1, r2, r3, ad);
                vfr[j2 * 2][0] = r0; vfr[j2 * 2][1] = r1;
                vfr[j2 * 2 + 1][0] = r2; vfr[j2 * 2 + 1][1] = r3;
            }
            #pragma unroll
            for (int j = 0; j < 8; j++)
                mma16816(oacc[j], pa, vfr[j]);
        }
    }

    // write O (normalized) as fp16 into o16[row][h*64+e]
    float inv0 = 1.f / l[0], inv1 = 1.f / l[1];
    int cg = (lane & 3) * 2;
    #pragma unroll
    for (int j = 0; j < 8; j++) {
        size_t r0 = (size_t)(b * T + trow0);
        size_t r1 = r0 + 8;
        int c = h * HD + j * 8 + cg;
        *(__half2*)(o16 + r0 * D + c) = __floats2half2_rn(oacc[j][0] * inv0, oacc[j][1] * inv0);
        *(__half2*)(o16 + r1 * D + c) = __floats2half2_rn(oacc[j][2] * inv1, oacc[j][3] * inv1);
    }
}

// ---------------------------------------------------------------------------
// Host orchestration
// ---------------------------------------------------------------------------
extern "C" void kernel_launch(void* const* d_in, const int* in_sizes, int n_in,
                              void* d_out, int out_size) {
    (void)in_sizes; (void)n_in; (void)out_size;
    const int*   x      = (const int*)  d_in[0];
    const float* tok    = (const float*)d_in[1];
    const float* pos    = (const float*)d_in[2];
    const float* Wq     = (const float*)d_in[3];
    const float* Wk     = (const float*)d_in[4];
    const float* Wv     = (const float*)d_in[5];
    const float* Wproj  = (const float*)d_in[6];
    const float* bproj  = (const float*)d_in[7];
    const float* ln1_g  = (const float*)d_in[8];
    const float* ln1_b  = (const float*)d_in[9];
    const float* ln2_g  = (const float*)d_in[10];
    const float* ln2_b  = (const float*)d_in[11];
    const float* W1     = (const float*)d_in[12];
    const float* b1     = (const float*)d_in[13];
    const float* W2     = (const float*)d_in[14];
    const float* b2     = (const float*)d_in[15];
    const float* lnf_g  = (const float*)d_in[16];
    const float* lnf_b  = (const float*)d_in[17];
    const float* Wlm    = (const float*)d_in[18];
    const float* blm    = (const float*)d_in[19];
    float* out = (float*)d_out;

    float *h_;
    __half *a16, *qkv16, *f16, *o16, *b16;
    cudaGetSymbolAddress((void**)&h_,    g_h);
    cudaGetSymbolAddress((void**)&a16,   g_a16);
    cudaGetSymbolAddress((void**)&qkv16, g_qkv16);
    cudaGetSymbolAddress((void**)&f16,   g_f16);
    cudaGetSymbolAddress((void**)&o16,   g_o16);
    cudaGetSymbolAddress((void**)&b16,   g_b16);

    embed_kernel<<<MROWS, 256>>>(x, tok, pos, h_);

    for (int l = 0; l < NL; l++) {
        const float* wq = Wq + (size_t)l * H * D * HD;
        const float* wk = Wk + (size_t)l * H * D * HD;
        const float* wv = Wv + (size_t)l * H * D * HD;

        layernorm_kernel<<<MROWS, 256>>>(h_, ln1_g + l * D, ln1_b + l * D, a16);

        // fused QKV: pack B = [3072][1024], one GEMM -> qkv16 fp16
        convQKV_kernel<<<dim3(HD / 32, D / 32, H), 256>>>(wq, b16);
        convQKV_kernel<<<dim3(HD / 32, D / 32, H), 256>>>(wk, b16 + (size_t)D * D);
        convQKV_kernel<<<dim3(HD / 32, D / 32, H), 256>>>(wv, b16 + (size_t)2 * D * D);
        gemm_mma_kernel<<<dim3(3 * D / 128, MROWS / 128), 256>>>(
            a16, b16, nullptr, nullptr, nullptr, qkv16, 3 * D, D, 0);

        // fused causal attention -> o16 fp16
        flash_attn_kernel<<<dim3(T / 64, BATCH * H), 128>>>(qkv16, o16);

        // output projection + residual (fp32 h)
        convT_kernel<<<dim3(D / 32, D / 32), 256>>>(Wproj + (size_t)l * D * D, b16, D, D);
        gemm_mma_kernel<<<dim3(D / 128, MROWS / 128), 256>>>(
            o16, b16, bproj + l * D, h_, h_, nullptr, D, D, 0);

        // MLP
        layernorm_kernel<<<MROWS, 256>>>(h_, ln2_g + l * D, ln2_b + l * D, a16);
        convT_kernel<<<dim3(DF / 32, D / 32), 256>>>(W1 + (size_t)l * D * DF, b16, D, DF);
        gemm_mma_kernel<<<dim3(DF / 128, MROWS / 128), 256>>>(
            a16, b16, b1 + l * DF, nullptr, nullptr, f16, DF, D, 1);
        convT_kernel<<<dim3(D / 32, DF / 32), 256>>>(W2 + (size_t)l * DF * D, b16, DF, D);
        gemm_mma_kernel<<<dim3(D / 128, MROWS / 128), 256>>>(
            f16, b16, b2 + l * D, h_, h_, nullptr, D, DF, 0);
    }

    // Final LN + LM head (fp32 out)
    layernorm_kernel<<<MROWS, 256>>>(h_, lnf_g, lnf_b, a16);
    convT_kernel<<<dim3(VOCAB / 32, D / 32), 256>>>(Wlm, b16, D, VOCAB);
    gemm_mma_kernel<<<dim3(VOCAB / 128, MROWS / 128), 256>>>(
        a16, b16, blm, nullptr, out, nullptr, VOCAB, D, 0);
}

// round 6
// speedup vs baseline: 6.6017x; 1.0876x over previous
#include <cuda_runtime.h>
#include <cuda_fp16.h>
#include <cstdint>

// ---------------------------------------------------------------------------
// PoetryGPT forward: fp16 HMMA GEMMs with in-flight fp32->fp16 B conversion
// + fused flash attention. B=2,T=1024,D=1024,H=16,HD=64,L=8,V=32000,DF=4096
// ---------------------------------------------------------------------------

namespace {
constexpr int BATCH = 2;
constexpr int T     = 1024;
constexpr int D     = 1024;
constexpr int H     = 16;
constexpr int HD    = 64;
constexpr int NL    = 8;
constexpr int VOCAB = 32000;
constexpr int DF    = 4096;
constexpr int MROWS = BATCH * T;      // 2048
}

// Scratch (static device globals; no allocation anywhere)
__device__ float  g_h    [MROWS * D];
__device__ __half g_a16  [(size_t)MROWS * D];
__device__ __half g_qkv16[(size_t)MROWS * 3 * D];
__device__ __half g_f16  [(size_t)MROWS * DF];
__device__ __half g_o16  [(size_t)MROWS * D];

// ---------------------------------------------------------------------------
__device__ __forceinline__ uint32_t smem_u32(const void* p) {
    uint32_t a;
    asm("{ .reg .u64 t; cvta.to.shared.u64 t, %1; cvt.u32.u64 %0, t; }"
        : "=r"(a) : "l"(p));
    return a;
}
#define CP_ASYNC16(sa, gp) \
    asm volatile("cp.async.cg.shared.global [%0], [%1], 16;" :: "r"(sa), "l"(gp))
#define CP_COMMIT() asm volatile("cp.async.commit_group;" ::: "memory")

__device__ __forceinline__ void ldmatrix_x4(uint32_t& r0, uint32_t& r1,
                                            uint32_t& r2, uint32_t& r3,
                                            uint32_t addr) {
    asm volatile("ldmatrix.sync.aligned.m8n8.x4.shared.b16 {%0,%1,%2,%3}, [%4];"
                 : "=r"(r0), "=r"(r1), "=r"(r2), "=r"(r3) : "r"(addr));
}
__device__ __forceinline__ void ldmatrix_x4_trans(uint32_t& r0, uint32_t& r1,
                                                  uint32_t& r2, uint32_t& r3,
                                                  uint32_t addr) {
    asm volatile("ldmatrix.sync.aligned.m8n8.x4.trans.shared.b16 {%0,%1,%2,%3}, [%4];"
                 : "=r"(r0), "=r"(r1), "=r"(r2), "=r"(r3) : "r"(addr));
}
__device__ __forceinline__ void mma16816(float* c, const uint32_t* a,
                                         const uint32_t* b) {
    asm volatile(
        "mma.sync.aligned.m16n8k16.row.col.f32.f16.f16.f32 "
        "{%0,%1,%2,%3}, {%4,%5,%6,%7}, {%8,%9}, {%0,%1,%2,%3};"
        : "+f"(c[0]), "+f"(c[1]), "+f"(c[2]), "+f"(c[3])
        : "r"(a[0]), "r"(a[1]), "r"(a[2]), "r"(a[3]), "r"(b[0]), "r"(b[1]));
}
__device__ __forceinline__ uint32_t h2pack(float x, float y) {
    __half2 h = __floats2half2_rn(x, y);
    return *(uint32_t*)&h;
}

// ---------------------------------------------------------------------------
// Block reductions (blockDim.x == 256)
// ---------------------------------------------------------------------------
__device__ __forceinline__ float blk_sum(float v) {
    __shared__ float sm[8];
    int lane = threadIdx.x & 31, w = threadIdx.x >> 5;
    #pragma unroll
    for (int o = 16; o; o >>= 1) v += __shfl_xor_sync(0xffffffffu, v, o);
    if (lane == 0) sm[w] = v;
    __syncthreads();
    if (w == 0) {
        float x = (lane < 8) ? sm[lane] : 0.f;
        #pragma unroll
        for (int o = 4; o; o >>= 1) x += __shfl_xor_sync(0xffffffffu, x, o);
        if (lane == 0) sm[0] = x;
    }
    __syncthreads();
    float r = sm[0];
    __syncthreads();
    return r;
}

// ---------------------------------------------------------------------------
// Embedding
// ---------------------------------------------------------------------------
__global__ void embed_kernel(const int* __restrict__ x,
                             const float* __restrict__ tok,
                             const float* __restrict__ pos,
                             float* __restrict__ out) {
    int row = blockIdx.x;
    int t   = row & (T - 1);
    int id  = x[row];
    int c   = threadIdx.x * 4;
    float4 a = *(const float4*)(tok + (size_t)id * D + c);
    float4 p = *(const float4*)(pos + (size_t)t * D + c);
    float4 r; r.x = a.x + p.x; r.y = a.y + p.y; r.z = a.z + p.z; r.w = a.w + p.w;
    *(float4*)(out + (size_t)row * D + c) = r;
}

// ---------------------------------------------------------------------------
// LayerNorm over D=1024, fp32 in -> fp16 out
// ---------------------------------------------------------------------------
__global__ void layernorm_kernel(const float* __restrict__ x,
                                 const float* __restrict__ g,
                                 const float* __restrict__ b,
                                 __half* __restrict__ y) {
    int row = blockIdx.x;
    int c   = threadIdx.x * 4;
    float4 v = *(const float4*)(x + (size_t)row * D + c);
    float mean = blk_sum(v.x + v.y + v.z + v.w) * (1.f / D);
    float dx = v.x - mean, dy = v.y - mean, dz = v.z - mean, dw = v.w - mean;
    float var = blk_sum(dx * dx + dy * dy + dz * dz + dw * dw) * (1.f / D);
    float inv = rsqrtf(var + 1e-5f);
    float4 gv = *(const float4*)(g + c);
    float4 bv = *(const float4*)(b + c);
    __half2* o = (__half2*)(y + (size_t)row * D + c);
    o[0] = __floats2half2_rn(dx * inv * gv.x + bv.x, dy * inv * gv.y + bv.y);
    o[1] = __floats2half2_rn(dz * inv * gv.z + bv.z, dw * inv * gv.w + bv.w);
}

// ---------------------------------------------------------------------------
// HMMA GEMM with in-flight B conversion:
//   C[M,N] = A[M,K](fp16) @ B[K,N](fp32) (+bias)(+res)(relu)
// B is the native fp32 weight, row-major [K,N]. qkv!=0 selects the
// (H,D,HD) layout across three tensors B0/B1/B2 (cols 0..1023 -> B0, etc.).
// BM=BN=128, BK=32, 256 threads (8 warps 4x2). A via cp.async double-buffer;
// B via register-prefetched LDG.128 + in-register cvt -> smem fp16.
// ---------------------------------------------------------------------------
__global__ void __launch_bounds__(256)
gemm_wf32_kernel(const __half* __restrict__ A,
                 const float* __restrict__ B0, const float* __restrict__ B1,
                 const float* __restrict__ B2,
                 const float* __restrict__ bias, const float* res,
                 float* __restrict__ Cf, __half* __restrict__ Ch,
                 int N, int K, int relu, int qkv) {
    __shared__ __half sA[2][128 * 40];
    __shared__ __half sB[2][32 * 136];   // [k][n], 136-half row stride

    int tid = threadIdx.x, lane = tid & 31, wid = tid >> 5;
    int wm = wid & 3, wn = wid >> 2;
    size_t m0 = (size_t)blockIdx.y * 128, n0 = (size_t)blockIdx.x * 128;

    // ---- A cp.async mapping (2 x 16B per thread per tile) ----
    int lr  = tid >> 2;
    int seg = (tid & 3) * 8;
    const __half* Ag0 = A + (m0 + lr) * (size_t)K + seg;
    const __half* Ag1 = A + (m0 + lr + 64) * (size_t)K + seg;
    uint32_t sa0 = smem_u32(&sA[0][lr * 40 + seg]);
    uint32_t sa1 = smem_u32(&sA[0][(lr + 64) * 40 + seg]);
    const uint32_t bufstepA = 128 * 40 * 2;

    // ---- B load mapping: 4 x float4 per thread per tile ----
    // linear = tid + i*256 ; row = linear>>5 (0..31) ; segcol = tid&31
    int brow = tid >> 5;          // + i*8
    int bseg = tid & 31;          // col group (4 floats)
    int ncol = (int)n0 + bseg * 4;
    const float* Bsel = B0;
    int nloc = ncol;
    if (qkv) {
        int s = ncol >> 10;
        Bsel = (s == 0) ? B0 : ((s == 1) ? B1 : B2);
        nloc = ncol & 1023;
    }
    int hh = nloc >> 6, ee = nloc & 63;   // qkv decomposition

    float4 breg[4];
    auto loadB = [&](int kb) {
        #pragma unroll
        for (int i = 0; i < 4; i++) {
            int k = kb * 32 + brow + i * 8;
            const float* p = qkv
                ? (Bsel + ((size_t)hh * D + k) * HD + ee)
                : (Bsel + (size_t)k * N + nloc);
            breg[i] = *(const float4*)p;
        }
    };
    auto storeB = [&](int buf) {
        #pragma unroll
        for (int i = 0; i < 4; i++) {
            int row = brow + i * 8;
            uint2 pk;
            pk.x = h2pack(breg[i].x, breg[i].y);
            pk.y = h2pack(breg[i].z, breg[i].w);
            *(uint2*)&sB[buf][row * 136 + bseg * 4] = pk;
        }
    };

    float acc[2][8][4] = {};
    int nk = K >> 5;

    // prologue: A chunk0 async, B chunk0 regs
    CP_ASYNC16(sa0, Ag0);
    CP_ASYNC16(sa1, Ag1);
    CP_COMMIT();
    loadB(0);

    for (int kb = 0; kb < nk; kb++) {
        int buf = kb & 1;
        storeB(buf);
        bool more = (kb + 1) < nk;
        if (more) {
            uint32_t bo = ((kb + 1) & 1) * bufstepA;
            size_t go = (size_t)(kb + 1) * 32;
            CP_ASYNC16(sa0 + bo, Ag0 + go);
            CP_ASYNC16(sa1 + bo, Ag1 + go);
            CP_COMMIT();
            asm volatile("cp.async.wait_group 1;" ::: "memory");
        } else {
            asm volatile("cp.async.wait_group 0;" ::: "memory");
        }
        __syncthreads();
        if (more) loadB(kb + 1);   // LDGs overlap the MMA section below

        #pragma unroll
        for (int ks = 0; ks < 2; ks++) {
            uint32_t a[2][4], b[8][2];
            #pragma unroll
            for (int mt = 0; mt < 2; mt++) {
                uint32_t ad = smem_u32(
                    &sA[buf][(wm * 32 + mt * 16 + (lane & 15)) * 40 +
                             ks * 16 + (lane >> 4) * 8]);
                ldmatrix_x4(a[mt][0], a[mt][1], a[mt][2], a[mt][3], ad);
            }
            #pragma unroll
            for (int j2 = 0; j2 < 4; j2++) {
                uint32_t r0, r1, r2, r3;
                uint32_t bd = smem_u32(
                    &sB[buf][(ks * 16 + (lane & 15)) * 136 +
                             wn * 64 + j2 * 16 + (lane >> 4) * 8]);
                ldmatrix_x4_trans(r0, r1, r2, r3, bd);
                b[j2 * 2][0] = r0; b[j2 * 2][1] = r1;
                b[j2 * 2 + 1][0] = r2; b[j2 * 2 + 1][1] = r3;
            }
            #pragma unroll
            for (int mt = 0; mt < 2; mt++)
                #pragma unroll
                for (int nt = 0; nt < 8; nt++)
                    mma16816(acc[mt][nt], a[mt], b[nt]);
        }
        __syncthreads();
    }

    int rg = lane >> 2, cg = (lane & 3) * 2;
    #pragma unroll
    for (int mt = 0; mt < 2; mt++) {
        #pragma unroll
        for (int half = 0; half < 2; half++) {
            size_t r = m0 + wm * 32 + mt * 16 + rg + half * 8;
            #pragma unroll
            for (int nt = 0; nt < 8; nt++) {
                size_t c = n0 + wn * 64 + nt * 8 + cg;
                float vx = acc[mt][nt][half * 2 + 0];
                float vy = acc[mt][nt][half * 2 + 1];
                if (bias) { vx += bias[c]; vy += bias[c + 1]; }
                if (res) {
                    float2 rv = *(const float2*)(res + r * N + c);
                    vx += rv.x; vy += rv.y;
                }
                if (relu) { vx = fmaxf(vx, 0.f); vy = fmaxf(vy, 0.f); }
                if (Ch) {
                    *(__half2*)(Ch + r * N + c) = __floats2half2_rn(vx, vy);
                } else {
                    float2 v; v.x = vx; v.y = vy;
                    *(float2*)(Cf + r * N + c) = v;
                }
            }
        }
    }
}

// ---------------------------------------------------------------------------
// Fused causal flash attention (fp16 HMMA, fp32 online softmax)
// qkv: [row][3*D] fp16 (q at h*64, k at 1024+h*64, v at 2048+h*64)
// o16: [row][D] fp16. grid (T/64, BATCH*H), block 128 (4 warps)
// ---------------------------------------------------------------------------
__global__ void __launch_bounds__(128)
flash_attn_kernel(const __half* __restrict__ qkv, __half* __restrict__ o16) {
    constexpr int RS = 3 * D;
    constexpr int ST = 72;
    __shared__ __half sQ[64 * ST];
    __shared__ __half sK[2][64 * ST];
    __shared__ __half sV[2][64 * ST];

    int tid = threadIdx.x, lane = tid & 31, wid = tid >> 5;
    int bh = blockIdx.y;
    int b = bh >> 4, h = bh & 15;
    int tt = blockIdx.x, t0 = tt * 64;

    const __half* qb = qkv + (size_t)(b * T) * RS + h * HD;
    const __half* kb = qb + D;
    const __half* vb = qb + 2 * D;

    int seg = (tid & 7) * 8, rr = tid >> 3;
    #pragma unroll
    for (int i = 0; i < 4; i++) {
        int row = rr + i * 16;
        *(uint4*)&sQ[row * ST + seg] =
            *(const uint4*)(qb + (size_t)(t0 + row) * RS + seg);
    }
    __syncthreads();

    uint32_t qa[4][4];
    {
        int qr = wid * 16 + (lane & 15);
        #pragma unroll
        for (int kk = 0; kk < 4; kk++) {
            uint32_t ad = smem_u32(&sQ[qr * ST + kk * 16 + (lane >> 4) * 8]);
            ldmatrix_x4(qa[kk][0], qa[kk][1], qa[kk][2], qa[kk][3], ad);
        }
    }

    float m[2] = {-1e30f, -1e30f}, l[2] = {0.f, 0.f};
    float oacc[8][4] = {};
    int nst = tt + 1;

    {
        #pragma unroll
        for (int i = 0; i < 4; i++) {
            int row = rr + i * 16;
            CP_ASYNC16(smem_u32(&sK[0][row * ST + seg]), kb + (size_t)row * RS + seg);
            CP_ASYNC16(smem_u32(&sV[0][row * ST + seg]), vb + (size_t)row * RS + seg);
        }
        CP_COMMIT();
    }

    const float scale = 0.03125f;
    int trow0 = t0 + wid * 16 + (lane >> 2);

    for (int st = 0; st < nst; st++) {
        int buf = st & 1;
        asm volatile("cp.async.wait_group 0;" ::: "memory");
        __syncthreads();
        if (st + 1 < nst) {
            int nb = buf ^ 1;
            #pragma unroll
            for (int i = 0; i < 4; i++) {
                int row = rr + i * 16;
                const __half* kg = kb + (size_t)((st + 1) * 64 + row) * RS + seg;
                const __half* vg = vb + (size_t)((st + 1) * 64 + row) * RS + seg;
                CP_ASYNC16(smem_u32(&sK[nb][row * ST + seg]), kg);
                CP_ASYNC16(smem_u32(&sV[nb][row * ST + seg]), vg);
            }
            CP_COMMIT();
        }

        float sacc[8][4] = {};
        #pragma unroll
        for (int kk = 0; kk < 4; kk++) {
            uint32_t bfr[8][2];
            #pragma unroll
            for (int j2 = 0; j2 < 4; j2++) {
                uint32_t r0, r1, r2, r3;
                uint32_t ad = smem_u32(
                    &sK[buf][(j2 * 16 + (lane & 15)) * ST + kk * 16 + (lane >> 4) * 8]);
                ldmatrix_x4(r0, r1, r2, r3, ad);
                bfr[j2 * 2][0] = r0; bfr[j2 * 2][1] = r2;
                bfr[j2 * 2 + 1][0] = r1; bfr[j2 * 2 + 1][1] = r3;
            }
            #pragma unroll
            for (int j = 0; j < 8; j++)
                mma16816(sacc[j], qa[kk], bfr[j]);
        }

        bool diag = (st == tt);
        #pragma unroll
        for (int j = 0; j < 8; j++) {
            #pragma unroll
            for (int q = 0; q < 4; q++) {
                float v = sacc[j][q] * scale;
                if (diag) {
                    int s = st * 64 + j * 8 + (lane & 3) * 2 + (q & 1);
                    int t = trow0 + ((q < 2) ? 0 : 8);
                    if (s > t) v = -1e30f;
                }
                sacc[j][q] = v;
            }
        }

        float mx0 = -1e30f, mx1 = -1e30f;
        #pragma unroll
        for (int j = 0; j < 8; j++) {
            mx0 = fmaxf(mx0, fmaxf(sacc[j][0], sacc[j][1]));
            mx1 = fmaxf(mx1, fmaxf(sacc[j][2], sacc[j][3]));
        }
        #pragma unroll
        for (int o = 1; o <= 2; o <<= 1) {
            mx0 = fmaxf(mx0, __shfl_xor_sync(0xffffffffu, mx0, o));
            mx1 = fmaxf(mx1, __shfl_xor_sync(0xffffffffu, mx1, o));
        }
        float mn0 = fmaxf(m[0], mx0), mn1 = fmaxf(m[1], mx1);
        float a0 = __expf(m[0] - mn0), a1 = __expf(m[1] - mn1);
        m[0] = mn0; m[1] = mn1;

        float s0 = 0.f, s1 = 0.f;
        #pragma unroll
        for (int j = 0; j < 8; j++) {
            sacc[j][0] = __expf(sacc[j][0] - mn0);
            sacc[j][1] = __expf(sacc[j][1] - mn0);
            sacc[j][2] = __expf(sacc[j][2] - mn1);
            sacc[j][3] = __expf(sacc[j][3] - mn1);
            s0 += sacc[j][0] + sacc[j][1];
            s1 += sacc[j][2] + sacc[j][3];
        }
        #pragma unroll
        for (int o = 1; o <= 2; o <<= 1) {
            s0 += __shfl_xor_sync(0xffffffffu, s0, o);
            s1 += __shfl_xor_sync(0xffffffffu, s1, o);
        }
        l[0] = l[0] * a0 + s0;
        l[1] = l[1] * a1 + s1;
        #pragma unroll
        for (int j = 0; j < 8; j++) {
            oacc[j][0] *= a0; oacc[j][1] *= a0;
            oacc[j][2] *= a1; oacc[j][3] *= a1;
        }

        #pragma unroll
        for (int kk = 0; kk < 4; kk++) {
            uint32_t pa[4];
            pa[0] = h2pack(sacc[2 * kk][0], sacc[2 * kk][1]);
            pa[1] = h2pack(sacc[2 * kk][2], sacc[2 * kk][3]);
            pa[2] = h2pack(sacc[2 * kk + 1][0], sacc[2 * kk + 1][1]);
            pa[3] = h2pack(sacc[2 * kk + 1][2], sacc[2 * kk + 1][3]);
            uint32_t vfr[8][2];
            #pragma unroll
            for (int j2 = 0; j2 < 4; j2++) {
                uint32_t r0, r1, r2, r3;
                uint32_t ad = smem_u32(
                    &sV[buf][(kk * 16 + (lane & 15)) * ST + j2 * 16 + (lane >> 4) * 8]);
                ldmatrix_x4_trans(r0, r1, r2, r3, ad);
                vfr[j2 * 2][0] = r0; vfr[j2 * 2][1] = r1;
                vfr[j2 * 2 + 1][0] = r2; vfr[j2 * 2 + 1][1] = r3;
            }
            #pragma unroll
            for (int j = 0; j < 8; j++)
                mma16816(oacc[j], pa, vfr[j]);
        }
    }

    float inv0 = 1.f / l[0], inv1 = 1.f / l[1];
    int cg = (lane & 3) * 2;
    #pragma unroll
    for (int j = 0; j < 8; j++) {
        size_t r0 = (size_t)(b * T + trow0);
        size_t r1 = r0 + 8;
        int c = h * HD + j * 8 + cg;
        *(__half2*)(o16 + r0 * D + c) = __floats2half2_rn(oacc[j][0] * inv0, oacc[j][1] * inv0);
        *(__half2*)(o16 + r1 * D + c) = __floats2half2_rn(oacc[j][2] * inv1, oacc[j][3] * inv1);
    }
}

// ---------------------------------------------------------------------------
// Host orchestration
// ---------------------------------------------------------------------------
extern "C" void kernel_launch(void* const* d_in, const int* in_sizes, int n_in,
                              void* d_out, int out_size) {
    (void)in_sizes; (void)n_in; (void)out_size;
    const int*   x      = (const int*)  d_in[0];
    const float* tok    = (const float*)d_in[1];
    const float* pos    = (const float*)d_in[2];
    const float* Wq     = (const float*)d_in[3];
    const float* Wk     = (const float*)d_in[4];
    const float* Wv     = (const float*)d_in[5];
    const float* Wproj  = (const float*)d_in[6];
    const float* bproj  = (const float*)d_in[7];
    const float* ln1_g  = (const float*)d_in[8];
    const float* ln1_b  = (const float*)d_in[9];
    const float* ln2_g  = (const float*)d_in[10];
    const float* ln2_b  = (const float*)d_in[11];
    const float* W1     = (const float*)d_in[12];
    const float* b1     = (const float*)d_in[13];
    const float* W2     = (const float*)d_in[14];
    const float* b2     = (const float*)d_in[15];
    const float* lnf_g  = (const float*)d_in[16];
    const float* lnf_b  = (const float*)d_in[17];
    const float* Wlm    = (const float*)d_in[18];
    const float* blm    = (const float*)d_in[19];
    float* out = (float*)d_out;

    float *h_;
    __half *a16, *qkv16, *f16, *o16;
    cudaGetSymbolAddress((void**)&h_,    g_h);
    cudaGetSymbolAddress((void**)&a16,   g_a16);
    cudaGetSymbolAddress((void**)&qkv16, g_qkv16);
    cudaGetSymbolAddress((void**)&f16,   g_f16);
    cudaGetSymbolAddress((void**)&o16,   g_o16);

    embed_kernel<<<MROWS, 256>>>(x, tok, pos, h_);

    for (int l = 0; l < NL; l++) {
        const float* wq = Wq + (size_t)l * H * D * HD;
        const float* wk = Wk + (size_t)l * H * D * HD;
        const float* wv = Wv + (size_t)l * H * D * HD;

        layernorm_kernel<<<MROWS, 256>>>(h_, ln1_g + l * D, ln1_b + l * D, a16);

        // fused QKV GEMM directly on fp32 (H,D,HD) weights
        gemm_wf32_kernel<<<dim3(3 * D / 128, MROWS / 128), 256>>>(
            a16, wq, wk, wv, nullptr, nullptr, nullptr, qkv16, 3 * D, D, 0, 1);

        // fused causal attention -> o16 fp16
        flash_attn_kernel<<<dim3(T / 64, BATCH * H), 128>>>(qkv16, o16);

        // output projection + residual (fp32 h)
        gemm_wf32_kernel<<<dim3(D / 128, MROWS / 128), 256>>>(
            o16, Wproj + (size_t)l * D * D, nullptr, nullptr,
            bproj + l * D, h_, h_, nullptr, D, D, 0, 0);

        // MLP
        layernorm_kernel<<<MROWS, 256>>>(h_, ln2_g + l * D, ln2_b + l * D, a16);
        gemm_wf32_kernel<<<dim3(DF / 128, MROWS / 128), 256>>>(
            a16, W1 + (size_t)l * D * DF, nullptr, nullptr,
            b1 + l * DF, nullptr, nullptr, f16, DF, D, 1, 0);
        gemm_wf32_kernel<<<dim3(D / 128, MROWS / 128), 256>>>(
            f16, W2 + (size_t)l * DF * D, nullptr, nullptr,
            b2 + l * D, h_, h_, nullptr, D, DF, 0, 0);
    }

    // Final LN + LM head (fp32 out)
    layernorm_kernel<<<MROWS, 256>>>(h_, lnf_g, lnf_b, a16);
    gemm_wf32_kernel<<<dim3(VOCAB / 128, MROWS / 128), 256>>>(
        a16, Wlm, nullptr, nullptr, blm, nullptr, out, nullptr, VOCAB, D, 0, 0);
}